// round 13
// baseline (speedup 1.0000x reference)
#include <cuda_runtime.h>
#include <cuda_bf16.h>
#include <cstdint>
#include <math.h>

#define BB 4
#define LL 2048
#define DD 1024
#define HH 16
#define DHD 64
#define ROWS (BB*LL)   // 8192
#define K2 2048        // split-K: (hi,lo) bf16 pairs interleaved

// ---------------------------------------------------------------------------
// Scratch (__device__ globals: allocation-free rule)
// ---------------------------------------------------------------------------
__device__ float g_proj[ROWS*DD];
__device__ float g_mad[BB*LL];               // mask addend: ok? -36 : -inf

__device__ __nv_bfloat16 g_q2[ROWS*K2];
__device__ __nv_bfloat16 g_k2[ROWS*K2];
__device__ __nv_bfloat16 g_v2[ROWS*K2];
__device__ __nv_bfloat16 g_att2[ROWS*K2];
__device__ __nv_bfloat16 g_Wq2[DD*K2];
__device__ __nv_bfloat16 g_Wk2[DD*K2];
__device__ __nv_bfloat16 g_Wv2[DD*K2];
__device__ __nv_bfloat16 g_Wo2[DD*K2];

__device__ __nv_bfloat16 g_qbf[BB*HH*LL*DHD];  // [b,h,l,64]
__device__ __nv_bfloat16 g_kbf[BB*HH*LL*DHD];  // [b,h,l,64]
__device__ __nv_bfloat16 g_vt [BB*HH*DHD*LL];  // [b,h,64,L]

// ---------------------------------------------------------------------------
__device__ __forceinline__ uint32_t smem_u32(const void* p) {
    uint32_t a;
    asm("{ .reg .u64 t; cvta.to.shared.u64 t, %1; cvt.u32.u64 %0, t; }"
        : "=r"(a) : "l"(p));
    return a;
}

__device__ __forceinline__ void ldm_x4(uint32_t addr, uint32_t* r) {
    asm volatile("ldmatrix.sync.aligned.m8n8.x4.shared.b16 {%0,%1,%2,%3}, [%4];"
        : "=r"(r[0]), "=r"(r[1]), "=r"(r[2]), "=r"(r[3]) : "r"(addr));
}

__device__ __forceinline__ void mma16816(float* c, const uint32_t* a,
                                         uint32_t b0, uint32_t b1) {
    asm volatile(
        "mma.sync.aligned.m16n8k16.row.col.f32.bf16.bf16.f32 "
        "{%0,%1,%2,%3}, {%4,%5,%6,%7}, {%8,%9}, {%0,%1,%2,%3};"
        : "+f"(c[0]), "+f"(c[1]), "+f"(c[2]), "+f"(c[3])
        : "r"(a[0]), "r"(a[1]), "r"(a[2]), "r"(a[3]), "r"(b0), "r"(b1));
}

__device__ __forceinline__ uint32_t pack_bf162(float lo, float hi) {
    __nv_bfloat162 t = __floats2bfloat162_rn(lo, hi);
    return *(uint32_t*)&t;
}

__device__ __forceinline__ float ex2f(float x) {
    float r;
    asm("ex2.approx.f32 %0, %1;" : "=f"(r) : "f"(x));
    return r;
}

#define CP16(dst, src) \
    asm volatile("cp.async.cg.shared.global [%0], [%1], 16;" \
        :: "r"(dst), "l"(src))
#define CP_COMMIT() asm volatile("cp.async.commit_group;")
#define CP_WAIT0()  asm volatile("cp.async.wait_group 0;")
#define CP_WAIT1()  asm volatile("cp.async.wait_group 1;")
#define CP_WAIT2()  asm volatile("cp.async.wait_group 2;")

#define SM_C2  0.180336880f   // 0.125 * log2(e)
#define SM_B2  36.0f
#define ONESF  0x3f803f80u    // bf16x2 (1.0, 1.0)

// ---------------------------------------------------------------------------
// fp32 -> (hi,lo) bf16 split, interleaved; batched over gridDim.y tensors
// ---------------------------------------------------------------------------
__device__ __forceinline__ void split_one(const float* in,
                                          __nv_bfloat16* out, int i)
{
    float4 x = ((const float4*)in)[i];
    union { __nv_bfloat162 h2[4]; uint4 u; } pk;
    {
        __nv_bfloat16 h = __float2bfloat16(x.x);
        pk.h2[0] = __halves2bfloat162(h, __float2bfloat16(x.x - __bfloat162float(h)));
    }
    {
        __nv_bfloat16 h = __float2bfloat16(x.y);
        pk.h2[1] = __halves2bfloat162(h, __float2bfloat16(x.y - __bfloat162float(h)));
    }
    {
        __nv_bfloat16 h = __float2bfloat16(x.z);
        pk.h2[2] = __halves2bfloat162(h, __float2bfloat16(x.z - __bfloat162float(h)));
    }
    {
        __nv_bfloat16 h = __float2bfloat16(x.w);
        pk.h2[3] = __halves2bfloat162(h, __float2bfloat16(x.w - __bfloat162float(h)));
    }
    ((uint4*)out)[i] = pk.u;
}

__global__ __launch_bounds__(256) void split3_kernel(
    const float* __restrict__ a, const float* __restrict__ b,
    const float* __restrict__ c,
    __nv_bfloat16* __restrict__ oa, __nv_bfloat16* __restrict__ ob,
    __nv_bfloat16* __restrict__ oc, int n4)
{
    int i = blockIdx.x * blockDim.x + threadIdx.x;
    if (i >= n4) return;
    const float* in = (blockIdx.y == 0) ? a : (blockIdx.y == 1) ? b : c;
    __nv_bfloat16* out = (blockIdx.y == 0) ? oa : (blockIdx.y == 1) ? ob : oc;
    split_one(in, out, i);
}

__global__ __launch_bounds__(256) void split4_kernel(
    const float* __restrict__ a, const float* __restrict__ b,
    const float* __restrict__ c, const float* __restrict__ d,
    __nv_bfloat16* __restrict__ oa, __nv_bfloat16* __restrict__ ob,
    __nv_bfloat16* __restrict__ oc, __nv_bfloat16* __restrict__ od, int n4)
{
    int i = blockIdx.x * blockDim.x + threadIdx.x;
    if (i >= n4) return;
    const float* in = (blockIdx.y == 0) ? a : (blockIdx.y == 1) ? b
                    : (blockIdx.y == 2) ? c : d;
    __nv_bfloat16* out = (blockIdx.y == 0) ? oa : (blockIdx.y == 1) ? ob
                       : (blockIdx.y == 2) ? oc : od;
    split_one(in, out, i);
}

// mask int -> float addend (once, 8192 elems)
__global__ __launch_bounds__(256) void mask_kernel(
    const int* __restrict__ mask, float* __restrict__ mad)
{
    int i = blockIdx.x * blockDim.x + threadIdx.x;
    if (i < BB * LL)
        mad[i] = (mask[i] != 0) ? -SM_B2 : __int_as_float(0xff800000);
}

// ---------------------------------------------------------------------------
// GEMM core v2: CTA tile 256x128, 8 warps (4m x 2n), warp tile 64x64,
// K-chunk 32, 4-stage cp.async pipeline, ONE __syncthreads per chunk.
// smem: A 4 x 256x80 = 80 KB, B 4 x 128x80 = 40 KB  (120 KB, 1 CTA/SM).
// ---------------------------------------------------------------------------
#define KCH   32
#define NCHNK (K2 / KCH)    // 64
#define PITCH 80
#define ABUF  (256*PITCH)   // 20480
#define BBUF  (128*PITCH)   // 10240
#define BOFF  (4*ABUF)      // 81920
#define GM_SMEM (4*ABUF + 4*BBUF)   // 122880

__device__ __forceinline__ void gemm_mainloop(
    const __nv_bfloat16* A2, const __nv_bfloat16* W2,
    int m0, int n0, uint32_t smBase,
    int tid, int lane, int wm, int wn,
    float acc[4][8][4])
{
    // A: thread t loads row t (256 rows), 64B = 4 x CP16
    const char* agp = (const char*)(A2 + (size_t)(m0 + tid) * K2);
    const uint32_t stA0 = smBase + tid * PITCH;
    // B: thread pair per row (128 rows), 32B each = 2 x CP16
    const int gr2 = tid >> 1;
    const int sb2 = (tid & 1) * 2;
    const char* bgp = (const char*)(W2 + (size_t)(n0 + gr2) * K2) + sb2 * 16;
    const uint32_t stB0 = smBase + BOFF + gr2 * PITCH + sb2 * 16;

#pragma unroll
    for (int p = 0; p < 2; p++) {
        const char* sA = agp + p * 64;
        const char* sB = bgp + p * 64;
#pragma unroll
        for (int s = 0; s < 4; s++) CP16(stA0 + p * ABUF + s * 16, sA + s * 16);
        CP16(stB0 + p * BBUF,      sB);
        CP16(stB0 + p * BBUF + 16, sB + 16);
        CP_COMMIT();
    }

    const uint32_t lrow = (uint32_t)(lane & 15) * PITCH + (uint32_t)(lane >> 4) * 16;

    #pragma unroll 1
    for (int c = 0; c < NCHNK; c++) {
        const int buf = c & 3;

        if (c + 2 < NCHNK) {
            const int nb = (c + 2) & 3;
            const char* sA = agp + (c + 2) * 64;
            const char* sB = bgp + (c + 2) * 64;
#pragma unroll
            for (int s = 0; s < 4; s++) CP16(stA0 + nb * ABUF + s * 16, sA + s * 16);
            CP16(stB0 + nb * BBUF,      sB);
            CP16(stB0 + nb * BBUF + 16, sB + 16);
            CP_COMMIT();
            CP_WAIT2();
        } else if (c + 1 < NCHNK) {
            CP_WAIT1();
        } else {
            CP_WAIT0();
        }
        __syncthreads();

        const uint32_t baseA = smBase + buf * ABUF + lrow;
        const uint32_t baseB = smBase + BOFF + buf * BBUF + lrow;

#pragma unroll
        for (int ks = 0; ks < 2; ks++) {
            uint32_t afr[4][4];
#pragma unroll
            for (int mt = 0; mt < 4; mt++)
                ldm_x4(baseA + (wm * 64 + mt * 16) * PITCH + ks * 32, afr[mt]);
#pragma unroll
            for (int ng = 0; ng < 4; ng++) {
                uint32_t bfr[4];
                ldm_x4(baseB + (wn * 64 + ng * 16) * PITCH + ks * 32, bfr);
#pragma unroll
                for (int mt = 0; mt < 4; mt++) {
                    mma16816(acc[mt][ng * 2 + 0], afr[mt], bfr[0], bfr[2]);
                    mma16816(acc[mt][ng * 2 + 1], afr[mt], bfr[1], bfr[3]);
                }
            }
        }
    }
}

// Merged Q/K/V projection GEMM. grid (8, 32, 3); z: 0=Q, 1=K, 2=V.
__global__ __launch_bounds__(256) void gemm_qkv(
    const __nv_bfloat16* __restrict__ q2, const __nv_bfloat16* __restrict__ k2,
    const __nv_bfloat16* __restrict__ v2,
    const __nv_bfloat16* __restrict__ Wq2, const __nv_bfloat16* __restrict__ Wk2,
    const __nv_bfloat16* __restrict__ Wv2,
    const float* __restrict__ bq, const float* __restrict__ bk,
    const float* __restrict__ bv,
    __nv_bfloat16* __restrict__ qbf, __nv_bfloat16* __restrict__ kbf,
    __nv_bfloat16* __restrict__ vt)
{
    extern __shared__ __align__(16) char gsm[];

    const int z = blockIdx.z;
    const __nv_bfloat16* A2 = (z == 0) ? q2 : (z == 1) ? k2 : v2;
    const __nv_bfloat16* W2 = (z == 0) ? Wq2 : (z == 1) ? Wk2 : Wv2;
    const float* bias = (z == 0) ? bq : (z == 1) ? bk : bv;

    const int tid  = threadIdx.x;
    const int lane = tid & 31;
    const int w    = tid >> 5;
    const int wm   = w & 3;
    const int wn   = w >> 2;
    const int m0   = blockIdx.y * 256;
    const int n0   = blockIdx.x * 128;

    float acc[4][8][4];
#pragma unroll
    for (int i = 0; i < 4; i++)
#pragma unroll
        for (int j = 0; j < 8; j++)
#pragma unroll
            for (int l = 0; l < 4; l++) acc[i][j][l] = 0.0f;

    gemm_mainloop(A2, W2, m0, n0, smem_u32(gsm), tid, lane, wm, wn, acc);

    const int r0 = lane >> 2;
    const int c0 = (lane & 3) * 2;

    if (z != 2) {
        __nv_bfloat162* C = (__nv_bfloat162*)((z == 0) ? qbf : kbf);
#pragma unroll
        for (int mt = 0; mt < 4; mt++) {
#pragma unroll
            for (int nt = 0; nt < 8; nt++) {
                int row = m0 + wm * 64 + mt * 16 + r0;
                int col = n0 + wn * 64 + nt * 8 + c0;
                float2 bb = *(const float2*)(bias + col);
                int bI = row >> 11, lI = row & (LL - 1);
                int hI = col >> 6,  dI = col & 63;
                size_t off = ((((size_t)bI * HH + hI) * LL + lI) * 64 + dI) >> 1;
                C[off] = __floats2bfloat162_rn(
                    acc[mt][nt][0] + bb.x, acc[mt][nt][1] + bb.y);
                C[off + 256] = __floats2bfloat162_rn(     // row+8: +8*64/2
                    acc[mt][nt][2] + bb.x, acc[mt][nt][3] + bb.y);
            }
        }
    } else {
        // V: transposed bf16 out [b,h,64,L] via smem stage [128 cols][256+8]
        __syncthreads();
        __nv_bfloat16* stage = (__nv_bfloat16*)gsm;
#pragma unroll
        for (int mt = 0; mt < 4; mt++) {
#pragma unroll
            for (int nt = 0; nt < 8; nt++) {
                int rl = wm * 64 + mt * 16 + r0;
                int cl = wn * 64 + nt * 8 + c0;
                float2 bb = *(const float2*)(bias + n0 + cl);
                stage[cl       * 264 + rl]     = __float2bfloat16(acc[mt][nt][0] + bb.x);
                stage[(cl + 1) * 264 + rl]     = __float2bfloat16(acc[mt][nt][1] + bb.y);
                stage[cl       * 264 + rl + 8] = __float2bfloat16(acc[mt][nt][2] + bb.x);
                stage[(cl + 1) * 264 + rl + 8] = __float2bfloat16(acc[mt][nt][3] + bb.y);
            }
        }
        __syncthreads();
        const int bI = m0 >> 11, lI = m0 & (LL - 1);
        const int drow = tid >> 1, seg = tid & 1;   // col, half (128 elems each)
        const int hI = (n0 + drow) >> 6, dI = (n0 + drow) & 63;
        const uint4* src = (const uint4*)(stage + drow * 264 + seg * 128);
        uint4* dst = (uint4*)(vt + (((size_t)bI * HH + hI) * DHD + dI) * LL
                              + lI + seg * 128);
#pragma unroll
        for (int i = 0; i < 16; i++) dst[i] = src[i];
    }
}

// Output projection GEMM (fp32 out). grid (8, 32).
__global__ __launch_bounds__(256) void gemm_o(
    const __nv_bfloat16* __restrict__ A2, const __nv_bfloat16* __restrict__ W2,
    const float* __restrict__ bias, float* __restrict__ C)
{
    extern __shared__ __align__(16) char gsm[];

    const int tid  = threadIdx.x;
    const int lane = tid & 31;
    const int w    = tid >> 5;
    const int wm   = w & 3;
    const int wn   = w >> 2;
    const int m0   = blockIdx.y * 256;
    const int n0   = blockIdx.x * 128;

    float acc[4][8][4];
#pragma unroll
    for (int i = 0; i < 4; i++)
#pragma unroll
        for (int j = 0; j < 8; j++)
#pragma unroll
            for (int l = 0; l < 4; l++) acc[i][j][l] = 0.0f;

    gemm_mainloop(A2, W2, m0, n0, smem_u32(gsm), tid, lane, wm, wn, acc);

    const int r0 = lane >> 2;
    const int c0 = (lane & 3) * 2;
#pragma unroll
    for (int mt = 0; mt < 4; mt++) {
#pragma unroll
        for (int nt = 0; nt < 8; nt++) {
            int row = m0 + wm * 64 + mt * 16 + r0;
            int col = n0 + wn * 64 + nt * 8 + c0;
            float2 bb = *(const float2*)(bias + col);
            float2 v0 = { acc[mt][nt][0] + bb.x, acc[mt][nt][1] + bb.y };
            float2 v1 = { acc[mt][nt][2] + bb.x, acc[mt][nt][3] + bb.y };
            *(float2*)(C + (size_t)row * DD + col)       = v0;
            *(float2*)(C + (size_t)(row + 8) * DD + col) = v1;
        }
    }
}

// ---------------------------------------------------------------------------
// Flash attention, fixed-bound softmax; row sums via tensor core (P @ ones).
// ---------------------------------------------------------------------------
#define QP 144
#define VP 272
#define SQ_OFF 0
#define SQ_SZ  (128*QP)
#define SK_OFF SQ_SZ
#define SK_SZ  (128*QP)
#define SV_OFF (SK_OFF + 2*SK_SZ)
#define SV_SZ  (64*VP)
#define MS_OFF (SV_OFF + 2*SV_SZ)
#define FL_SMEM (MS_OFF + 2*512)   // 91136

__global__ __launch_bounds__(256) void flash_tc(
    const __nv_bfloat16* __restrict__ Qb, const __nv_bfloat16* __restrict__ Kb,
    const __nv_bfloat16* __restrict__ Vt, const float* __restrict__ mad,
    __nv_bfloat16* __restrict__ att2)
{
    extern __shared__ __align__(16) char dyn[];

    const int b = blockIdx.z, h = blockIdx.y;
    const int q0 = blockIdx.x * 128;
    const int tid = threadIdx.x, lane = tid & 31, w = tid >> 5;
    const size_t bh = (size_t)b * HH + h;
    const uint32_t dynb = smem_u32(dyn);

    const char* ksrc0 = (const char*)(Kb + bh * LL * 64);
    const char* vsrc0 = (const char*)(Vt + bh * DHD * LL);
    const char* msrc0 = (const char*)(mad + b * LL);

    auto issue_tile = [&](int t, int buf) {
        const uint32_t kb = dynb + SK_OFF + buf * SK_SZ;
        const uint32_t vb = dynb + SV_OFF + buf * SV_SZ;
        const char* ks = ksrc0 + (size_t)t * 128 * 128;
#pragma unroll
        for (int j = 0; j < 4; j++) {
            int i = tid + 256 * j;
            int r = i >> 3, s = i & 7;
            CP16(kb + r * QP + s * 16, ks + r * 128 + s * 16);
        }
#pragma unroll
        for (int j = 0; j < 4; j++) {
            int i = tid + 256 * j;
            int r = i >> 4, s = i & 15;
            CP16(vb + r * VP + s * 16,
                 vsrc0 + ((size_t)r * LL + t * 128) * 2 + s * 16);
        }
        if (tid < 32)
            CP16(dynb + MS_OFF + buf * 512 + tid * 16,
                 msrc0 + (size_t)t * 512 + tid * 16);
    };

    {
        const char* qsrc = (const char*)(Qb + (bh * LL + q0) * 64);
#pragma unroll
        for (int j = 0; j < 4; j++) {
            int i = tid + 256 * j;
            int r = i >> 3, s = i & 7;
            *(uint4*)(dyn + SQ_OFF + r * QP + s * 16) =
                *(const uint4*)(qsrc + r * 128 + s * 16);
        }
    }
    issue_tile(0, 0);
    CP_COMMIT();
    __syncthreads();

    uint32_t qf[4][4];
    {
        uint32_t base = dynb + SQ_OFF + (w * 16 + (lane & 15)) * QP + (lane >> 4) * 16;
#pragma unroll
        for (int ks = 0; ks < 4; ks++) ldm_x4(base + ks * 32, qf[ks]);
    }

    float O[8][4];
#pragma unroll
    for (int g = 0; g < 8; g++)
#pragma unroll
        for (int l = 0; l < 4; l++) O[g][l] = 0.0f;
    float La[4] = {0.f, 0.f, 0.f, 0.f};

    const int c0 = (lane & 3) * 2;

    #pragma unroll 1
    for (int t = 0; t < LL / 128; t++) {
        const int buf = t & 1;
        if (t + 1 < LL / 128) {
            issue_tile(t + 1, buf ^ 1);
            CP_COMMIT();
            CP_WAIT1();
        } else {
            CP_WAIT0();
        }
        __syncthreads();

        const float* Msf = (const float*)(dyn + MS_OFF + buf * 512);

        float s[16][4];
        {
            uint32_t kbase = dynb + SK_OFF + buf * SK_SZ
                           + (lane & 15) * QP + (lane >> 4) * 16;
#pragma unroll
            for (int j = 0; j < 8; j++) {
                float a0[4] = {0, 0, 0, 0}, a1[4] = {0, 0, 0, 0};
#pragma unroll
                for (int ks = 0; ks < 4; ks++) {
                    uint32_t bf[4];
                    ldm_x4(kbase + j * 16 * QP + ks * 32, bf);
                    mma16816(a0, qf[ks], bf[0], bf[2]);
                    mma16816(a1, qf[ks], bf[1], bf[3]);
                }
#pragma unroll
                for (int l = 0; l < 4; l++) { s[2*j][l] = a0[l]; s[2*j+1][l] = a1[l]; }
            }
        }

#pragma unroll
        for (int j = 0; j < 16; j++) {
            int key = j * 8 + c0;
            float ad0 = Msf[key], ad1 = Msf[key + 1];
            s[j][0] = ex2f(fmaf(s[j][0], SM_C2, ad0));
            s[j][1] = ex2f(fmaf(s[j][1], SM_C2, ad1));
            s[j][2] = ex2f(fmaf(s[j][2], SM_C2, ad0));
            s[j][3] = ex2f(fmaf(s[j][3], SM_C2, ad1));
        }

        {
            uint32_t vbase = dynb + SV_OFF + buf * SV_SZ
                           + (lane & 15) * VP + (lane >> 4) * 16;
#pragma unroll
            for (int tt = 0; tt < 8; tt++) {
                uint32_t a[4];
                a[0] = pack_bf162(s[2*tt][0],   s[2*tt][1]);
                a[1] = pack_bf162(s[2*tt][2],   s[2*tt][3]);
                a[2] = pack_bf162(s[2*tt+1][0], s[2*tt+1][1]);
                a[3] = pack_bf162(s[2*tt+1][2], s[2*tt+1][3]);
                mma16816(La, a, ONESF, ONESF);
#pragma unroll
                for (int g = 0; g < 4; g++) {
                    uint32_t bf[4];
                    ldm_x4(vbase + g * 16 * VP + tt * 32, bf);
                    mma16816(O[2*g],     a, bf[0], bf[2]);
                    mma16816(O[2*g + 1], a, bf[1], bf[3]);
                }
            }
        }
        __syncthreads();
    }

    float inv0 = 1.0f / La[0], inv1 = 1.0f / La[2];
    const int r0 = lane >> 2;
    const size_t row0 = (size_t)b * LL + q0 + w * 16 + r0;
#pragma unroll
    for (int g = 0; g < 8; g++) {
        int d = 8 * g + c0;
        int cb = 2 * (h * DHD + d);
        float v0 = O[g][0] * inv0, v1 = O[g][1] * inv0;
        float v2 = O[g][2] * inv1, v3 = O[g][3] * inv1;
        union { __nv_bfloat162 h2[2]; uint2 u; } p0, p1;
        {
            __nv_bfloat16 hh = __float2bfloat16(v0);
            p0.h2[0] = __halves2bfloat162(hh, __float2bfloat16(v0 - __bfloat162float(hh)));
            hh = __float2bfloat16(v1);
            p0.h2[1] = __halves2bfloat162(hh, __float2bfloat16(v1 - __bfloat162float(hh)));
            hh = __float2bfloat16(v2);
            p1.h2[0] = __halves2bfloat162(hh, __float2bfloat16(v2 - __bfloat162float(hh)));
            hh = __float2bfloat16(v3);
            p1.h2[1] = __halves2bfloat162(hh, __float2bfloat16(v3 - __bfloat162float(hh)));
        }
        *(uint2*)(att2 + row0 * K2 + cb)       = p0.u;
        *(uint2*)(att2 + (row0 + 8) * K2 + cb) = p1.u;
    }
}

// ---------------------------------------------------------------------------
// Residual + LayerNorm
// ---------------------------------------------------------------------------
__global__ __launch_bounds__(256) void ln_kernel(
    const float* __restrict__ proj, const float* __restrict__ resid,
    const float* __restrict__ gamma, const float* __restrict__ beta,
    float* __restrict__ out)
{
    const int row = blockIdx.x;
    const int tid = threadIdx.x;

    float4 p = ((const float4*)(proj  + row * DD))[tid];
    float4 r = ((const float4*)(resid + row * DD))[tid];
    float4 x = make_float4(p.x + r.x, p.y + r.y, p.z + r.z, p.w + r.w);

    float s  = x.x + x.y + x.z + x.w;
    float ss = x.x * x.x + x.y * x.y + x.z * x.z + x.w * x.w;

#pragma unroll
    for (int off = 16; off > 0; off >>= 1) {
        s  += __shfl_xor_sync(0xffffffffu, s,  off);
        ss += __shfl_xor_sync(0xffffffffu, ss, off);
    }

    __shared__ float rs[8], rss[8];
    __shared__ float mu_s, rstd_s;
    const int wid  = tid >> 5;
    const int lane = tid & 31;
    if (lane == 0) { rs[wid] = s; rss[wid] = ss; }
    __syncthreads();
    if (tid == 0) {
        float S = 0.f, SS = 0.f;
#pragma unroll
        for (int i = 0; i < 8; i++) { S += rs[i]; SS += rss[i]; }
        float mu  = S * (1.0f / DD);
        float var = SS * (1.0f / DD) - mu * mu;
        mu_s   = mu;
        rstd_s = rsqrtf(var + 1e-5f);
    }
    __syncthreads();

    float mu = mu_s, rstd = rstd_s;
    float4 g  = ((const float4*)gamma)[tid];
    float4 be = ((const float4*)beta)[tid];
    float4 o;
    o.x = (x.x - mu) * rstd * g.x + be.x;
    o.y = (x.y - mu) * rstd * g.y + be.y;
    o.z = (x.z - mu) * rstd * g.z + be.z;
    o.w = (x.w - mu) * rstd * g.w + be.w;
    ((float4*)(out + row * DD))[tid] = o;
}

// ---------------------------------------------------------------------------
extern "C" void kernel_launch(void* const* d_in, const int* in_sizes, int n_in,
                              void* d_out, int out_size)
{
    const float* query = (const float*)d_in[0];
    const float* key_  = (const float*)d_in[1];
    const float* value = (const float*)d_in[2];
    const int*   mask  = (const int*  )d_in[3];
    const float* Wq    = (const float*)d_in[4];
    const float* bq    = (const float*)d_in[5];
    const float* Wk    = (const float*)d_in[6];
    const float* bk    = (const float*)d_in[7];
    const float* Wv    = (const float*)d_in[8];
    const float* bv    = (const float*)d_in[9];
    const float* Wo    = (const float*)d_in[10];
    const float* bo    = (const float*)d_in[11];
    const float* gamma = (const float*)d_in[12];
    const float* beta  = (const float*)d_in[13];
    float* out = (float*)d_out;

    float *proj, *mad;
    cudaGetSymbolAddress((void**)&proj, g_proj);
    cudaGetSymbolAddress((void**)&mad,  g_mad);
    __nv_bfloat16 *q2, *k2, *v2, *att2, *Wq2, *Wk2, *Wv2, *Wo2, *qbf, *kbf, *vt;
    cudaGetSymbolAddress((void**)&q2,   g_q2);
    cudaGetSymbolAddress((void**)&k2,   g_k2);
    cudaGetSymbolAddress((void**)&v2,   g_v2);
    cudaGetSymbolAddress((void**)&att2, g_att2);
    cudaGetSymbolAddress((void**)&Wq2,  g_Wq2);
    cudaGetSymbolAddress((void**)&Wk2,  g_Wk2);
    cudaGetSymbolAddress((void**)&Wv2,  g_Wv2);
    cudaGetSymbolAddress((void**)&Wo2,  g_Wo2);
    cudaGetSymbolAddress((void**)&qbf,  g_qbf);
    cudaGetSymbolAddress((void**)&kbf,  g_kbf);
    cudaGetSymbolAddress((void**)&vt,   g_vt);

    cudaFuncSetAttribute(flash_tc,
        cudaFuncAttributeMaxDynamicSharedMemorySize, FL_SMEM);
    cudaFuncSetAttribute(gemm_qkv,
        cudaFuncAttributeMaxDynamicSharedMemorySize, GM_SMEM);
    cudaFuncSetAttribute(gemm_o,
        cudaFuncAttributeMaxDynamicSharedMemorySize, GM_SMEM);

    const int nInp4 = ROWS * DD / 4;
    const int nW4   = DD * DD / 4;
    split3_kernel<<<dim3((nInp4 + 255) / 256, 3), 256>>>(
        query, key_, value, q2, k2, v2, nInp4);
    split4_kernel<<<dim3((nW4 + 255) / 256, 4), 256>>>(
        Wq, Wk, Wv, Wo, Wq2, Wk2, Wv2, Wo2, nW4);
    mask_kernel<<<(BB * LL + 255) / 256, 256>>>(mask, mad);

    dim3 qkvgrid(DD / 128, ROWS / 256, 3);   // (8, 32, 3)
    gemm_qkv<<<qkvgrid, 256, GM_SMEM>>>(
        q2, k2, v2, Wq2, Wk2, Wv2, bq, bk, bv, qbf, kbf, vt);

    dim3 fgrid(LL / 128, HH, BB);            // (16, 16, 4)
    flash_tc<<<fgrid, 256, FL_SMEM>>>(qbf, kbf, vt, mad, att2);

    dim3 ogrid(DD / 128, ROWS / 256);        // (8, 32)
    gemm_o<<<ogrid, 256, GM_SMEM>>>(att2, Wo2, bo, proj);

    ln_kernel<<<ROWS, 256>>>(proj, query, gamma, beta, out);
}

// round 14
// speedup vs baseline: 1.2196x; 1.2196x over previous
#include <cuda_runtime.h>
#include <cuda_bf16.h>
#include <cstdint>
#include <math.h>

#define BB 4
#define LL 2048
#define DD 1024
#define HH 16
#define DHD 64
#define ROWS (BB*LL)   // 8192
#define K2 2048        // split-K: (hi,lo) bf16 pairs interleaved

// ---------------------------------------------------------------------------
// Scratch (__device__ globals: allocation-free rule)
// ---------------------------------------------------------------------------
__device__ float g_proj[ROWS*DD];
__device__ float g_mad[BB*LL];               // mask addend: ok? -36 : -inf

__device__ __nv_bfloat16 g_q2[ROWS*K2];
__device__ __nv_bfloat16 g_k2[ROWS*K2];
__device__ __nv_bfloat16 g_v2[ROWS*K2];
__device__ __nv_bfloat16 g_att2[ROWS*K2];
__device__ __nv_bfloat16 g_Wq2[DD*K2];
__device__ __nv_bfloat16 g_Wk2[DD*K2];
__device__ __nv_bfloat16 g_Wv2[DD*K2];
__device__ __nv_bfloat16 g_Wo2[DD*K2];

__device__ __nv_bfloat16 g_qbf[BB*HH*LL*DHD];  // [b,h,l,64]
__device__ __nv_bfloat16 g_kbf[BB*HH*LL*DHD];  // [b,h,l,64]
__device__ __nv_bfloat16 g_vt [BB*HH*DHD*LL];  // [b,h,64,L]

// ---------------------------------------------------------------------------
__device__ __forceinline__ uint32_t smem_u32(const void* p) {
    uint32_t a;
    asm("{ .reg .u64 t; cvta.to.shared.u64 t, %1; cvt.u32.u64 %0, t; }"
        : "=r"(a) : "l"(p));
    return a;
}

__device__ __forceinline__ void ldm_x4(uint32_t addr, uint32_t* r) {
    asm volatile("ldmatrix.sync.aligned.m8n8.x4.shared.b16 {%0,%1,%2,%3}, [%4];"
        : "=r"(r[0]), "=r"(r[1]), "=r"(r[2]), "=r"(r[3]) : "r"(addr));
}

__device__ __forceinline__ void mma16816(float* c, const uint32_t* a,
                                         uint32_t b0, uint32_t b1) {
    asm volatile(
        "mma.sync.aligned.m16n8k16.row.col.f32.bf16.bf16.f32 "
        "{%0,%1,%2,%3}, {%4,%5,%6,%7}, {%8,%9}, {%0,%1,%2,%3};"
        : "+f"(c[0]), "+f"(c[1]), "+f"(c[2]), "+f"(c[3])
        : "r"(a[0]), "r"(a[1]), "r"(a[2]), "r"(a[3]), "r"(b0), "r"(b1));
}

__device__ __forceinline__ uint32_t pack_bf162(float lo, float hi) {
    __nv_bfloat162 t = __floats2bfloat162_rn(lo, hi);
    return *(uint32_t*)&t;
}

__device__ __forceinline__ float ex2f(float x) {
    float r;
    asm("ex2.approx.f32 %0, %1;" : "=f"(r) : "f"(x));
    return r;
}

#define CP16(dst, src) \
    asm volatile("cp.async.cg.shared.global [%0], [%1], 16;" \
        :: "r"(dst), "l"(src))
#define CP_COMMIT() asm volatile("cp.async.commit_group;")
#define CP_WAIT0()  asm volatile("cp.async.wait_group 0;")
#define CP_WAIT1()  asm volatile("cp.async.wait_group 1;")
#define CP_WAIT2()  asm volatile("cp.async.wait_group 2;")

#define SM_C2  0.180336880f   // 0.125 * log2(e)
#define SM_B2  36.0f
#define ONESF  0x3f803f80u    // bf16x2 (1.0, 1.0)

// ---------------------------------------------------------------------------
// fp32 -> (hi,lo) bf16 split, interleaved; batched over gridDim.y tensors
// ---------------------------------------------------------------------------
__device__ __forceinline__ void split_one(const float* in,
                                          __nv_bfloat16* out, int i)
{
    float4 x = ((const float4*)in)[i];
    union { __nv_bfloat162 h2[4]; uint4 u; } pk;
    {
        __nv_bfloat16 h = __float2bfloat16(x.x);
        pk.h2[0] = __halves2bfloat162(h, __float2bfloat16(x.x - __bfloat162float(h)));
    }
    {
        __nv_bfloat16 h = __float2bfloat16(x.y);
        pk.h2[1] = __halves2bfloat162(h, __float2bfloat16(x.y - __bfloat162float(h)));
    }
    {
        __nv_bfloat16 h = __float2bfloat16(x.z);
        pk.h2[2] = __halves2bfloat162(h, __float2bfloat16(x.z - __bfloat162float(h)));
    }
    {
        __nv_bfloat16 h = __float2bfloat16(x.w);
        pk.h2[3] = __halves2bfloat162(h, __float2bfloat16(x.w - __bfloat162float(h)));
    }
    ((uint4*)out)[i] = pk.u;
}

__global__ __launch_bounds__(256) void split3_kernel(
    const float* __restrict__ a, const float* __restrict__ b,
    const float* __restrict__ c,
    __nv_bfloat16* __restrict__ oa, __nv_bfloat16* __restrict__ ob,
    __nv_bfloat16* __restrict__ oc, int n4)
{
    int i = blockIdx.x * blockDim.x + threadIdx.x;
    if (i >= n4) return;
    const float* in = (blockIdx.y == 0) ? a : (blockIdx.y == 1) ? b : c;
    __nv_bfloat16* out = (blockIdx.y == 0) ? oa : (blockIdx.y == 1) ? ob : oc;
    split_one(in, out, i);
}

__global__ __launch_bounds__(256) void split4_kernel(
    const float* __restrict__ a, const float* __restrict__ b,
    const float* __restrict__ c, const float* __restrict__ d,
    __nv_bfloat16* __restrict__ oa, __nv_bfloat16* __restrict__ ob,
    __nv_bfloat16* __restrict__ oc, __nv_bfloat16* __restrict__ od, int n4)
{
    int i = blockIdx.x * blockDim.x + threadIdx.x;
    if (i >= n4) return;
    const float* in = (blockIdx.y == 0) ? a : (blockIdx.y == 1) ? b
                    : (blockIdx.y == 2) ? c : d;
    __nv_bfloat16* out = (blockIdx.y == 0) ? oa : (blockIdx.y == 1) ? ob
                       : (blockIdx.y == 2) ? oc : od;
    split_one(in, out, i);
}

// mask int -> float addend (once, 8192 elems)
__global__ __launch_bounds__(256) void mask_kernel(
    const int* __restrict__ mask, float* __restrict__ mad)
{
    int i = blockIdx.x * blockDim.x + threadIdx.x;
    if (i < BB * LL)
        mad[i] = (mask[i] != 0) ? -SM_B2 : __int_as_float(0xff800000);
}

// ---------------------------------------------------------------------------
// GEMM core (R12 config): 256 thr, 8 warps (4m x 2n, warp tile 32x64),
// CTA tile 128x128, K-chunk 32, 4-stage cp.async, ONE sync per chunk.
// ---------------------------------------------------------------------------
#define KCH   32
#define NCHNK (K2 / KCH)    // 64
#define PITCH 80
#define BUFSZ (128*PITCH)   // 10240
#define GM_SMEM (8*BUFSZ)   // 81920

__device__ __forceinline__ void gemm_mainloop(
    const __nv_bfloat16* A2, const __nv_bfloat16* W2,
    int m0, int n0, uint32_t smBase,
    int tid, int lane, int wm, int wn,
    float acc[2][8][4])
{
    const int gr = tid >> 1;
    const int sb = (tid & 1) * 2;
    const char* agp = (const char*)(A2 + (size_t)(m0 + gr) * K2) + sb * 16;
    const char* bgp = (const char*)(W2 + (size_t)(n0 + gr) * K2) + sb * 16;
    const uint32_t stA0 = smBase + gr * PITCH + sb * 16;
    const uint32_t stB0 = smBase + 4 * BUFSZ + gr * PITCH + sb * 16;

#pragma unroll
    for (int p = 0; p < 2; p++) {
        const char* sA = agp + p * 64;
        const char* sB = bgp + p * 64;
        CP16(stA0 + p * BUFSZ,      sA);
        CP16(stA0 + p * BUFSZ + 16, sA + 16);
        CP16(stB0 + p * BUFSZ,      sB);
        CP16(stB0 + p * BUFSZ + 16, sB + 16);
        CP_COMMIT();
    }

    const uint32_t lrow = (uint32_t)(lane & 15) * PITCH + (uint32_t)(lane >> 4) * 16;

    #pragma unroll 1
    for (int c = 0; c < NCHNK; c++) {
        const int buf = c & 3;

        if (c + 2 < NCHNK) {
            const int nb = (c + 2) & 3;
            const char* sA = agp + (c + 2) * 64;
            const char* sB = bgp + (c + 2) * 64;
            CP16(stA0 + nb * BUFSZ,      sA);
            CP16(stA0 + nb * BUFSZ + 16, sA + 16);
            CP16(stB0 + nb * BUFSZ,      sB);
            CP16(stB0 + nb * BUFSZ + 16, sB + 16);
            CP_COMMIT();
            CP_WAIT2();
        } else if (c + 1 < NCHNK) {
            CP_WAIT1();
        } else {
            CP_WAIT0();
        }
        __syncthreads();

        const uint32_t baseA = smBase + buf * BUFSZ + lrow;
        const uint32_t baseB = smBase + (4 + buf) * BUFSZ + lrow;

#pragma unroll
        for (int ks = 0; ks < 2; ks++) {
            uint32_t afr[2][4];
#pragma unroll
            for (int mt = 0; mt < 2; mt++)
                ldm_x4(baseA + (wm * 32 + mt * 16) * PITCH + ks * 32, afr[mt]);
#pragma unroll
            for (int ng = 0; ng < 4; ng++) {
                uint32_t bfr[4];
                ldm_x4(baseB + (wn * 64 + ng * 16) * PITCH + ks * 32, bfr);
#pragma unroll
                for (int mt = 0; mt < 2; mt++) {
                    mma16816(acc[mt][ng * 2 + 0], afr[mt], bfr[0], bfr[2]);
                    mma16816(acc[mt][ng * 2 + 1], afr[mt], bfr[1], bfr[3]);
                }
            }
        }
    }
}

// Merged Q/K/V projection GEMM. grid (8, 64, 3); z: 0=Q, 1=K, 2=V.
__global__ __launch_bounds__(256) void gemm_qkv(
    const __nv_bfloat16* __restrict__ q2, const __nv_bfloat16* __restrict__ k2,
    const __nv_bfloat16* __restrict__ v2,
    const __nv_bfloat16* __restrict__ Wq2, const __nv_bfloat16* __restrict__ Wk2,
    const __nv_bfloat16* __restrict__ Wv2,
    const float* __restrict__ bq, const float* __restrict__ bk,
    const float* __restrict__ bv,
    __nv_bfloat16* __restrict__ qbf, __nv_bfloat16* __restrict__ kbf,
    __nv_bfloat16* __restrict__ vt)
{
    extern __shared__ __align__(16) char gsm[];

    const int z = blockIdx.z;
    const __nv_bfloat16* A2 = (z == 0) ? q2 : (z == 1) ? k2 : v2;
    const __nv_bfloat16* W2 = (z == 0) ? Wq2 : (z == 1) ? Wk2 : Wv2;
    const float* bias = (z == 0) ? bq : (z == 1) ? bk : bv;

    const int tid  = threadIdx.x;
    const int lane = tid & 31;
    const int w    = tid >> 5;
    const int wm   = w & 3;
    const int wn   = w >> 2;
    const int m0   = blockIdx.y * 128;
    const int n0   = blockIdx.x * 128;

    float acc[2][8][4];
#pragma unroll
    for (int i = 0; i < 2; i++)
#pragma unroll
        for (int j = 0; j < 8; j++)
#pragma unroll
            for (int l = 0; l < 4; l++) acc[i][j][l] = 0.0f;

    gemm_mainloop(A2, W2, m0, n0, smem_u32(gsm), tid, lane, wm, wn, acc);

    const int r0 = lane >> 2;
    const int c0 = (lane & 3) * 2;

    if (z != 2) {
        __nv_bfloat162* C = (__nv_bfloat162*)((z == 0) ? qbf : kbf);
#pragma unroll
        for (int mt = 0; mt < 2; mt++) {
#pragma unroll
            for (int nt = 0; nt < 8; nt++) {
                int row = m0 + wm * 32 + mt * 16 + r0;
                int col = n0 + wn * 64 + nt * 8 + c0;
                float2 bb = *(const float2*)(bias + col);
                int bI = row >> 11, lI = row & (LL - 1);
                int hI = col >> 6,  dI = col & 63;
                size_t off = ((((size_t)bI * HH + hI) * LL + lI) * 64 + dI) >> 1;
                C[off] = __floats2bfloat162_rn(
                    acc[mt][nt][0] + bb.x, acc[mt][nt][1] + bb.y);
                C[off + 256] = __floats2bfloat162_rn(
                    acc[mt][nt][2] + bb.x, acc[mt][nt][3] + bb.y);
            }
        }
    } else {
        __syncthreads();
        __nv_bfloat16* stage = (__nv_bfloat16*)gsm;
#pragma unroll
        for (int mt = 0; mt < 2; mt++) {
#pragma unroll
            for (int nt = 0; nt < 8; nt++) {
                int rl = wm * 32 + mt * 16 + r0;
                int cl = wn * 64 + nt * 8 + c0;
                float2 bb = *(const float2*)(bias + n0 + cl);
                stage[cl       * 136 + rl]     = __float2bfloat16(acc[mt][nt][0] + bb.x);
                stage[(cl + 1) * 136 + rl]     = __float2bfloat16(acc[mt][nt][1] + bb.y);
                stage[cl       * 136 + rl + 8] = __float2bfloat16(acc[mt][nt][2] + bb.x);
                stage[(cl + 1) * 136 + rl + 8] = __float2bfloat16(acc[mt][nt][3] + bb.y);
            }
        }
        __syncthreads();
        const int bI = m0 >> 11, lI = m0 & (LL - 1);
        const int drow = tid >> 1, seg = tid & 1;
        const int hI = (n0 + drow) >> 6, dI = (n0 + drow) & 63;
        const uint4* src = (const uint4*)(stage + drow * 136 + seg * 64);
        uint4* dst = (uint4*)(vt + (((size_t)bI * HH + hI) * DHD + dI) * LL
                              + lI + seg * 64);
#pragma unroll
        for (int i = 0; i < 8; i++) dst[i] = src[i];
    }
}

// Output projection GEMM (fp32 out). grid (8, 64).
__global__ __launch_bounds__(256) void gemm_o(
    const __nv_bfloat16* __restrict__ A2, const __nv_bfloat16* __restrict__ W2,
    const float* __restrict__ bias, float* __restrict__ C)
{
    extern __shared__ __align__(16) char gsm[];

    const int tid  = threadIdx.x;
    const int lane = tid & 31;
    const int w    = tid >> 5;
    const int wm   = w & 3;
    const int wn   = w >> 2;
    const int m0   = blockIdx.y * 128;
    const int n0   = blockIdx.x * 128;

    float acc[2][8][4];
#pragma unroll
    for (int i = 0; i < 2; i++)
#pragma unroll
        for (int j = 0; j < 8; j++)
#pragma unroll
            for (int l = 0; l < 4; l++) acc[i][j][l] = 0.0f;

    gemm_mainloop(A2, W2, m0, n0, smem_u32(gsm), tid, lane, wm, wn, acc);

    const int r0 = lane >> 2;
    const int c0 = (lane & 3) * 2;
#pragma unroll
    for (int mt = 0; mt < 2; mt++) {
#pragma unroll
        for (int nt = 0; nt < 8; nt++) {
            int row = m0 + wm * 32 + mt * 16 + r0;
            int col = n0 + wn * 64 + nt * 8 + c0;
            float2 bb = *(const float2*)(bias + col);
            float2 v0 = { acc[mt][nt][0] + bb.x, acc[mt][nt][1] + bb.y };
            float2 v1 = { acc[mt][nt][2] + bb.x, acc[mt][nt][3] + bb.y };
            *(float2*)(C + (size_t)row * DD + col)       = v0;
            *(float2*)(C + (size_t)(row + 8) * DD + col) = v1;
        }
    }
}

// ---------------------------------------------------------------------------
// Flash attention v3: fused QK->exp->PV per key-fragment pair; 2 CTAs/SM.
// Score regs live only within one j iteration (8 regs vs 64).
// ---------------------------------------------------------------------------
#define QP 144
#define VP 272
#define SQ_OFF 0
#define SQ_SZ  (128*QP)
#define SK_OFF SQ_SZ
#define SK_SZ  (128*QP)
#define SV_OFF (SK_OFF + 2*SK_SZ)
#define SV_SZ  (64*VP)
#define MS_OFF (SV_OFF + 2*SV_SZ)
#define FL_SMEM (MS_OFF + 2*512)   // 91136

__global__ __launch_bounds__(256, 2) void flash_tc(
    const __nv_bfloat16* __restrict__ Qb, const __nv_bfloat16* __restrict__ Kb,
    const __nv_bfloat16* __restrict__ Vt, const float* __restrict__ mad,
    __nv_bfloat16* __restrict__ att2)
{
    extern __shared__ __align__(16) char dyn[];

    const int b = blockIdx.z, h = blockIdx.y;
    const int q0 = blockIdx.x * 128;
    const int tid = threadIdx.x, lane = tid & 31, w = tid >> 5;
    const size_t bh = (size_t)b * HH + h;
    const uint32_t dynb = smem_u32(dyn);

    const char* ksrc0 = (const char*)(Kb + bh * LL * 64);
    const char* vsrc0 = (const char*)(Vt + bh * DHD * LL);
    const char* msrc0 = (const char*)(mad + b * LL);

    auto issue_tile = [&](int t, int buf) {
        const uint32_t kb = dynb + SK_OFF + buf * SK_SZ;
        const uint32_t vb = dynb + SV_OFF + buf * SV_SZ;
        const char* ks = ksrc0 + (size_t)t * 128 * 128;
#pragma unroll
        for (int j = 0; j < 4; j++) {
            int i = tid + 256 * j;
            int r = i >> 3, s = i & 7;
            CP16(kb + r * QP + s * 16, ks + r * 128 + s * 16);
        }
#pragma unroll
        for (int j = 0; j < 4; j++) {
            int i = tid + 256 * j;
            int r = i >> 4, s = i & 15;
            CP16(vb + r * VP + s * 16,
                 vsrc0 + ((size_t)r * LL + t * 128) * 2 + s * 16);
        }
        if (tid < 32)
            CP16(dynb + MS_OFF + buf * 512 + tid * 16,
                 msrc0 + (size_t)t * 512 + tid * 16);
    };

    {
        const char* qsrc = (const char*)(Qb + (bh * LL + q0) * 64);
#pragma unroll
        for (int j = 0; j < 4; j++) {
            int i = tid + 256 * j;
            int r = i >> 3, s = i & 7;
            *(uint4*)(dyn + SQ_OFF + r * QP + s * 16) =
                *(const uint4*)(qsrc + r * 128 + s * 16);
        }
    }
    issue_tile(0, 0);
    CP_COMMIT();
    __syncthreads();

    uint32_t qf[4][4];
    {
        uint32_t base = dynb + SQ_OFF + (w * 16 + (lane & 15)) * QP + (lane >> 4) * 16;
#pragma unroll
        for (int ks = 0; ks < 4; ks++) ldm_x4(base + ks * 32, qf[ks]);
    }

    float O[8][4];
#pragma unroll
    for (int g = 0; g < 8; g++)
#pragma unroll
        for (int l = 0; l < 4; l++) O[g][l] = 0.0f;
    float La[4] = {0.f, 0.f, 0.f, 0.f};

    const int c0 = (lane & 3) * 2;

    #pragma unroll 1
    for (int t = 0; t < LL / 128; t++) {
        const int buf = t & 1;
        if (t + 1 < LL / 128) {
            issue_tile(t + 1, buf ^ 1);
            CP_COMMIT();
            CP_WAIT1();
        } else {
            CP_WAIT0();
        }
        __syncthreads();

        const float* Msf = (const float*)(dyn + MS_OFF + buf * 512);
        const uint32_t kbase = dynb + SK_OFF + buf * SK_SZ
                             + (lane & 15) * QP + (lane >> 4) * 16;
        const uint32_t vbase = dynb + SV_OFF + buf * SV_SZ
                             + (lane & 15) * VP + (lane >> 4) * 16;

        // fused: per j (16 keys): QK scores -> exp -> rowsum mma -> PV
#pragma unroll
        for (int j = 0; j < 8; j++) {
            float a0[4] = {0, 0, 0, 0}, a1[4] = {0, 0, 0, 0};
#pragma unroll
            for (int ks = 0; ks < 4; ks++) {
                uint32_t bf[4];
                ldm_x4(kbase + j * 16 * QP + ks * 32, bf);
                mma16816(a0, qf[ks], bf[0], bf[2]);
                mma16816(a1, qf[ks], bf[1], bf[3]);
            }

            int key = j * 16 + c0;
            float ad0 = Msf[key],     ad1 = Msf[key + 1];
            float ad2 = Msf[key + 8], ad3 = Msf[key + 9];
            a0[0] = ex2f(fmaf(a0[0], SM_C2, ad0));
            a0[1] = ex2f(fmaf(a0[1], SM_C2, ad1));
            a0[2] = ex2f(fmaf(a0[2], SM_C2, ad0));
            a0[3] = ex2f(fmaf(a0[3], SM_C2, ad1));
            a1[0] = ex2f(fmaf(a1[0], SM_C2, ad2));
            a1[1] = ex2f(fmaf(a1[1], SM_C2, ad3));
            a1[2] = ex2f(fmaf(a1[2], SM_C2, ad2));
            a1[3] = ex2f(fmaf(a1[3], SM_C2, ad3));

            uint32_t a[4];
            a[0] = pack_bf162(a0[0], a0[1]);
            a[1] = pack_bf162(a0[2], a0[3]);
            a[2] = pack_bf162(a1[0], a1[1]);
            a[3] = pack_bf162(a1[2], a1[3]);
            mma16816(La, a, ONESF, ONESF);
#pragma unroll
            for (int g = 0; g < 4; g++) {
                uint32_t bf[4];
                ldm_x4(vbase + g * 16 * VP + j * 32, bf);
                mma16816(O[2*g],     a, bf[0], bf[2]);
                mma16816(O[2*g + 1], a, bf[1], bf[3]);
            }
        }
        __syncthreads();
    }

    float inv0 = 1.0f / La[0], inv1 = 1.0f / La[2];
    const int r0 = lane >> 2;
    const size_t row0 = (size_t)b * LL + q0 + w * 16 + r0;
#pragma unroll
    for (int g = 0; g < 8; g++) {
        int d = 8 * g + c0;
        int cb = 2 * (h * DHD + d);
        float v0 = O[g][0] * inv0, v1 = O[g][1] * inv0;
        float v2 = O[g][2] * inv1, v3 = O[g][3] * inv1;
        union { __nv_bfloat162 h2[2]; uint2 u; } p0, p1;
        {
            __nv_bfloat16 hh = __float2bfloat16(v0);
            p0.h2[0] = __halves2bfloat162(hh, __float2bfloat16(v0 - __bfloat162float(hh)));
            hh = __float2bfloat16(v1);
            p0.h2[1] = __halves2bfloat162(hh, __float2bfloat16(v1 - __bfloat162float(hh)));
            hh = __float2bfloat16(v2);
            p1.h2[0] = __halves2bfloat162(hh, __float2bfloat16(v2 - __bfloat162float(hh)));
            hh = __float2bfloat16(v3);
            p1.h2[1] = __halves2bfloat162(hh, __float2bfloat16(v3 - __bfloat162float(hh)));
        }
        *(uint2*)(att2 + row0 * K2 + cb)       = p0.u;
        *(uint2*)(att2 + (row0 + 8) * K2 + cb) = p1.u;
    }
}

// ---------------------------------------------------------------------------
// Residual + LayerNorm
// ---------------------------------------------------------------------------
__global__ __launch_bounds__(256) void ln_kernel(
    const float* __restrict__ proj, const float* __restrict__ resid,
    const float* __restrict__ gamma, const float* __restrict__ beta,
    float* __restrict__ out)
{
    const int row = blockIdx.x;
    const int tid = threadIdx.x;

    float4 p = ((const float4*)(proj  + row * DD))[tid];
    float4 r = ((const float4*)(resid + row * DD))[tid];
    float4 x = make_float4(p.x + r.x, p.y + r.y, p.z + r.z, p.w + r.w);

    float s  = x.x + x.y + x.z + x.w;
    float ss = x.x * x.x + x.y * x.y + x.z * x.z + x.w * x.w;

#pragma unroll
    for (int off = 16; off > 0; off >>= 1) {
        s  += __shfl_xor_sync(0xffffffffu, s,  off);
        ss += __shfl_xor_sync(0xffffffffu, ss, off);
    }

    __shared__ float rs[8], rss[8];
    __shared__ float mu_s, rstd_s;
    const int wid  = tid >> 5;
    const int lane = tid & 31;
    if (lane == 0) { rs[wid] = s; rss[wid] = ss; }
    __syncthreads();
    if (tid == 0) {
        float S = 0.f, SS = 0.f;
#pragma unroll
        for (int i = 0; i < 8; i++) { S += rs[i]; SS += rss[i]; }
        float mu  = S * (1.0f / DD);
        float var = SS * (1.0f / DD) - mu * mu;
        mu_s   = mu;
        rstd_s = rsqrtf(var + 1e-5f);
    }
    __syncthreads();

    float mu = mu_s, rstd = rstd_s;
    float4 g  = ((const float4*)gamma)[tid];
    float4 be = ((const float4*)beta)[tid];
    float4 o;
    o.x = (x.x - mu) * rstd * g.x + be.x;
    o.y = (x.y - mu) * rstd * g.y + be.y;
    o.z = (x.z - mu) * rstd * g.z + be.z;
    o.w = (x.w - mu) * rstd * g.w + be.w;
    ((float4*)(out + row * DD))[tid] = o;
}

// ---------------------------------------------------------------------------
extern "C" void kernel_launch(void* const* d_in, const int* in_sizes, int n_in,
                              void* d_out, int out_size)
{
    const float* query = (const float*)d_in[0];
    const float* key_  = (const float*)d_in[1];
    const float* value = (const float*)d_in[2];
    const int*   mask  = (const int*  )d_in[3];
    const float* Wq    = (const float*)d_in[4];
    const float* bq    = (const float*)d_in[5];
    const float* Wk    = (const float*)d_in[6];
    const float* bk    = (const float*)d_in[7];
    const float* Wv    = (const float*)d_in[8];
    const float* bv    = (const float*)d_in[9];
    const float* Wo    = (const float*)d_in[10];
    const float* bo    = (const float*)d_in[11];
    const float* gamma = (const float*)d_in[12];
    const float* beta  = (const float*)d_in[13];
    float* out = (float*)d_out;

    float *proj, *mad;
    cudaGetSymbolAddress((void**)&proj, g_proj);
    cudaGetSymbolAddress((void**)&mad,  g_mad);
    __nv_bfloat16 *q2, *k2, *v2, *att2, *Wq2, *Wk2, *Wv2, *Wo2, *qbf, *kbf, *vt;
    cudaGetSymbolAddress((void**)&q2,   g_q2);
    cudaGetSymbolAddress((void**)&k2,   g_k2);
    cudaGetSymbolAddress((void**)&v2,   g_v2);
    cudaGetSymbolAddress((void**)&att2, g_att2);
    cudaGetSymbolAddress((void**)&Wq2,  g_Wq2);
    cudaGetSymbolAddress((void**)&Wk2,  g_Wk2);
    cudaGetSymbolAddress((void**)&Wv2,  g_Wv2);
    cudaGetSymbolAddress((void**)&Wo2,  g_Wo2);
    cudaGetSymbolAddress((void**)&qbf,  g_qbf);
    cudaGetSymbolAddress((void**)&kbf,  g_kbf);
    cudaGetSymbolAddress((void**)&vt,   g_vt);

    cudaFuncSetAttribute(flash_tc,
        cudaFuncAttributeMaxDynamicSharedMemorySize, FL_SMEM);
    cudaFuncSetAttribute(gemm_qkv,
        cudaFuncAttributeMaxDynamicSharedMemorySize, GM_SMEM);
    cudaFuncSetAttribute(gemm_o,
        cudaFuncAttributeMaxDynamicSharedMemorySize, GM_SMEM);

    const int nInp4 = ROWS * DD / 4;
    const int nW4   = DD * DD / 4;
    split3_kernel<<<dim3((nInp4 + 255) / 256, 3), 256>>>(
        query, key_, value, q2, k2, v2, nInp4);
    split4_kernel<<<dim3((nW4 + 255) / 256, 4), 256>>>(
        Wq, Wk, Wv, Wo, Wq2, Wk2, Wv2, Wo2, nW4);
    mask_kernel<<<(BB * LL + 255) / 256, 256>>>(mask, mad);

    dim3 qkvgrid(DD / 128, ROWS / 128, 3);   // (8, 64, 3)
    gemm_qkv<<<qkvgrid, 256, GM_SMEM>>>(
        q2, k2, v2, Wq2, Wk2, Wv2, bq, bk, bv, qbf, kbf, vt);

    dim3 fgrid(LL / 128, HH, BB);            // (16, 16, 4)
    flash_tc<<<fgrid, 256, FL_SMEM>>>(qbf, kbf, vt, mad, att2);

    dim3 ogrid(DD / 128, ROWS / 128);        // (8, 64)
    gemm_o<<<ogrid, 256, GM_SMEM>>>(att2, Wo2, bo, proj);

    ln_kernel<<<ROWS, 256>>>(proj, query, gamma, beta, out);
}

// round 15
// speedup vs baseline: 1.8485x; 1.5156x over previous
#include <cuda_runtime.h>
#include <cuda_bf16.h>
#include <cstdint>
#include <math.h>

#define BB 4
#define LL 2048
#define DD 1024
#define HH 16
#define DHD 64
#define ROWS (BB*LL)   // 8192
#define KDIM 1024      // plain-bf16 GEMM K

// ---------------------------------------------------------------------------
// Scratch (__device__ globals: allocation-free rule)
// ---------------------------------------------------------------------------
__device__ float g_proj[ROWS*DD];
__device__ float g_mad[BB*LL];               // mask addend: ok? -36 : -inf

__device__ __nv_bfloat16 g_qc[ROWS*KDIM];    // bf16 casts of inputs
__device__ __nv_bfloat16 g_kc[ROWS*KDIM];
__device__ __nv_bfloat16 g_vc[ROWS*KDIM];
__device__ __nv_bfloat16 g_att[ROWS*DD];     // flash out, plain bf16
__device__ __nv_bfloat16 g_Wqc[DD*KDIM];
__device__ __nv_bfloat16 g_Wkc[DD*KDIM];
__device__ __nv_bfloat16 g_Wvc[DD*KDIM];
__device__ __nv_bfloat16 g_Woc[DD*KDIM];

__device__ __nv_bfloat16 g_qbf[BB*HH*LL*DHD];  // [b,h,l,64]
__device__ __nv_bfloat16 g_kbf[BB*HH*LL*DHD];  // [b,h,l,64]
__device__ __nv_bfloat16 g_vt [BB*HH*DHD*LL];  // [b,h,64,L]

// ---------------------------------------------------------------------------
__device__ __forceinline__ uint32_t smem_u32(const void* p) {
    uint32_t a;
    asm("{ .reg .u64 t; cvta.to.shared.u64 t, %1; cvt.u32.u64 %0, t; }"
        : "=r"(a) : "l"(p));
    return a;
}

__device__ __forceinline__ void ldm_x4(uint32_t addr, uint32_t* r) {
    asm volatile("ldmatrix.sync.aligned.m8n8.x4.shared.b16 {%0,%1,%2,%3}, [%4];"
        : "=r"(r[0]), "=r"(r[1]), "=r"(r[2]), "=r"(r[3]) : "r"(addr));
}

__device__ __forceinline__ void mma16816(float* c, const uint32_t* a,
                                         uint32_t b0, uint32_t b1) {
    asm volatile(
        "mma.sync.aligned.m16n8k16.row.col.f32.bf16.bf16.f32 "
        "{%0,%1,%2,%3}, {%4,%5,%6,%7}, {%8,%9}, {%0,%1,%2,%3};"
        : "+f"(c[0]), "+f"(c[1]), "+f"(c[2]), "+f"(c[3])
        : "r"(a[0]), "r"(a[1]), "r"(a[2]), "r"(a[3]), "r"(b0), "r"(b1));
}

__device__ __forceinline__ uint32_t pack_bf162(float lo, float hi) {
    __nv_bfloat162 t = __floats2bfloat162_rn(lo, hi);
    return *(uint32_t*)&t;
}

__device__ __forceinline__ float ex2f(float x) {
    float r;
    asm("ex2.approx.f32 %0, %1;" : "=f"(r) : "f"(x));
    return r;
}

#define CP16(dst, src) \
    asm volatile("cp.async.cg.shared.global [%0], [%1], 16;" \
        :: "r"(dst), "l"(src))
#define CP_COMMIT() asm volatile("cp.async.commit_group;")
#define CP_WAIT0()  asm volatile("cp.async.wait_group 0;")
#define CP_WAIT1()  asm volatile("cp.async.wait_group 1;")
#define CP_WAIT2()  asm volatile("cp.async.wait_group 2;")

#define SM_C2  0.180336880f   // 0.125 * log2(e)
#define SM_B2  36.0f
#define ONESF  0x3f803f80u    // bf16x2 (1.0, 1.0)

// ---------------------------------------------------------------------------
// fp32 -> bf16 cast; batched over gridDim.y tensors
// ---------------------------------------------------------------------------
__device__ __forceinline__ void cast_one(const float* in,
                                         __nv_bfloat16* out, int i)
{
    float4 x = ((const float4*)in)[i];
    uint2 o;
    o.x = pack_bf162(x.x, x.y);
    o.y = pack_bf162(x.z, x.w);
    ((uint2*)out)[i] = o;
}

__global__ __launch_bounds__(256) void cast3_kernel(
    const float* __restrict__ a, const float* __restrict__ b,
    const float* __restrict__ c,
    __nv_bfloat16* __restrict__ oa, __nv_bfloat16* __restrict__ ob,
    __nv_bfloat16* __restrict__ oc, int n4)
{
    int i = blockIdx.x * blockDim.x + threadIdx.x;
    if (i >= n4) return;
    const float* in = (blockIdx.y == 0) ? a : (blockIdx.y == 1) ? b : c;
    __nv_bfloat16* out = (blockIdx.y == 0) ? oa : (blockIdx.y == 1) ? ob : oc;
    cast_one(in, out, i);
}

__global__ __launch_bounds__(256) void cast4_kernel(
    const float* __restrict__ a, const float* __restrict__ b,
    const float* __restrict__ c, const float* __restrict__ d,
    __nv_bfloat16* __restrict__ oa, __nv_bfloat16* __restrict__ ob,
    __nv_bfloat16* __restrict__ oc, __nv_bfloat16* __restrict__ od, int n4)
{
    int i = blockIdx.x * blockDim.x + threadIdx.x;
    if (i >= n4) return;
    const float* in = (blockIdx.y == 0) ? a : (blockIdx.y == 1) ? b
                    : (blockIdx.y == 2) ? c : d;
    __nv_bfloat16* out = (blockIdx.y == 0) ? oa : (blockIdx.y == 1) ? ob
                       : (blockIdx.y == 2) ? oc : od;
    cast_one(in, out, i);
}

// mask int -> float addend (once, 8192 elems)
__global__ __launch_bounds__(256) void mask_kernel(
    const int* __restrict__ mask, float* __restrict__ mad)
{
    int i = blockIdx.x * blockDim.x + threadIdx.x;
    if (i < BB * LL)
        mad[i] = (mask[i] != 0) ? -SM_B2 : __int_as_float(0xff800000);
}

// ---------------------------------------------------------------------------
// GEMM core: 256 thr, 8 warps (4m x 2n, warp tile 32x64), CTA tile 128x128,
// K = 1024 (plain bf16), K-chunk 32, 4-stage cp.async, ONE sync per chunk.
// ---------------------------------------------------------------------------
#define KCH   32
#define NCHNK (KDIM / KCH)  // 32
#define PITCH 80
#define BUFSZ (128*PITCH)   // 10240
#define GM_SMEM (8*BUFSZ)   // 81920

__device__ __forceinline__ void gemm_mainloop(
    const __nv_bfloat16* A2, const __nv_bfloat16* W2,
    int m0, int n0, uint32_t smBase,
    int tid, int lane, int wm, int wn,
    float acc[2][8][4])
{
    const int gr = tid >> 1;
    const int sb = (tid & 1) * 2;
    const char* agp = (const char*)(A2 + (size_t)(m0 + gr) * KDIM) + sb * 16;
    const char* bgp = (const char*)(W2 + (size_t)(n0 + gr) * KDIM) + sb * 16;
    const uint32_t stA0 = smBase + gr * PITCH + sb * 16;
    const uint32_t stB0 = smBase + 4 * BUFSZ + gr * PITCH + sb * 16;

#pragma unroll
    for (int p = 0; p < 2; p++) {
        const char* sA = agp + p * 64;
        const char* sB = bgp + p * 64;
        CP16(stA0 + p * BUFSZ,      sA);
        CP16(stA0 + p * BUFSZ + 16, sA + 16);
        CP16(stB0 + p * BUFSZ,      sB);
        CP16(stB0 + p * BUFSZ + 16, sB + 16);
        CP_COMMIT();
    }

    const uint32_t lrow = (uint32_t)(lane & 15) * PITCH + (uint32_t)(lane >> 4) * 16;

    #pragma unroll 1
    for (int c = 0; c < NCHNK; c++) {
        const int buf = c & 3;

        if (c + 2 < NCHNK) {
            const int nb = (c + 2) & 3;
            const char* sA = agp + (c + 2) * 64;
            const char* sB = bgp + (c + 2) * 64;
            CP16(stA0 + nb * BUFSZ,      sA);
            CP16(stA0 + nb * BUFSZ + 16, sA + 16);
            CP16(stB0 + nb * BUFSZ,      sB);
            CP16(stB0 + nb * BUFSZ + 16, sB + 16);
            CP_COMMIT();
            CP_WAIT2();
        } else if (c + 1 < NCHNK) {
            CP_WAIT1();
        } else {
            CP_WAIT0();
        }
        __syncthreads();

        const uint32_t baseA = smBase + buf * BUFSZ + lrow;
        const uint32_t baseB = smBase + (4 + buf) * BUFSZ + lrow;

#pragma unroll
        for (int ks = 0; ks < 2; ks++) {
            uint32_t afr[2][4];
#pragma unroll
            for (int mt = 0; mt < 2; mt++)
                ldm_x4(baseA + (wm * 32 + mt * 16) * PITCH + ks * 32, afr[mt]);
#pragma unroll
            for (int ng = 0; ng < 4; ng++) {
                uint32_t bfr[4];
                ldm_x4(baseB + (wn * 64 + ng * 16) * PITCH + ks * 32, bfr);
#pragma unroll
                for (int mt = 0; mt < 2; mt++) {
                    mma16816(acc[mt][ng * 2 + 0], afr[mt], bfr[0], bfr[2]);
                    mma16816(acc[mt][ng * 2 + 1], afr[mt], bfr[1], bfr[3]);
                }
            }
        }
    }
}

// Merged Q/K/V projection GEMM. grid (8, 64, 3); z: 0=Q, 1=K, 2=V.
__global__ __launch_bounds__(256) void gemm_qkv(
    const __nv_bfloat16* __restrict__ qc, const __nv_bfloat16* __restrict__ kc,
    const __nv_bfloat16* __restrict__ vc,
    const __nv_bfloat16* __restrict__ Wqc, const __nv_bfloat16* __restrict__ Wkc,
    const __nv_bfloat16* __restrict__ Wvc,
    const float* __restrict__ bq, const float* __restrict__ bk,
    const float* __restrict__ bv,
    __nv_bfloat16* __restrict__ qbf, __nv_bfloat16* __restrict__ kbf,
    __nv_bfloat16* __restrict__ vt)
{
    extern __shared__ __align__(16) char gsm[];

    const int z = blockIdx.z;
    const __nv_bfloat16* A2 = (z == 0) ? qc : (z == 1) ? kc : vc;
    const __nv_bfloat16* W2 = (z == 0) ? Wqc : (z == 1) ? Wkc : Wvc;
    const float* bias = (z == 0) ? bq : (z == 1) ? bk : bv;

    const int tid  = threadIdx.x;
    const int lane = tid & 31;
    const int w    = tid >> 5;
    const int wm   = w & 3;
    const int wn   = w >> 2;
    const int m0   = blockIdx.y * 128;
    const int n0   = blockIdx.x * 128;

    float acc[2][8][4];
#pragma unroll
    for (int i = 0; i < 2; i++)
#pragma unroll
        for (int j = 0; j < 8; j++)
#pragma unroll
            for (int l = 0; l < 4; l++) acc[i][j][l] = 0.0f;

    gemm_mainloop(A2, W2, m0, n0, smem_u32(gsm), tid, lane, wm, wn, acc);

    const int r0 = lane >> 2;
    const int c0 = (lane & 3) * 2;

    if (z != 2) {
        __nv_bfloat162* C = (__nv_bfloat162*)((z == 0) ? qbf : kbf);
#pragma unroll
        for (int mt = 0; mt < 2; mt++) {
#pragma unroll
            for (int nt = 0; nt < 8; nt++) {
                int row = m0 + wm * 32 + mt * 16 + r0;
                int col = n0 + wn * 64 + nt * 8 + c0;
                float2 bb = *(const float2*)(bias + col);
                int bI = row >> 11, lI = row & (LL - 1);
                int hI = col >> 6,  dI = col & 63;
                size_t off = ((((size_t)bI * HH + hI) * LL + lI) * 64 + dI) >> 1;
                C[off] = __floats2bfloat162_rn(
                    acc[mt][nt][0] + bb.x, acc[mt][nt][1] + bb.y);
                C[off + 256] = __floats2bfloat162_rn(
                    acc[mt][nt][2] + bb.x, acc[mt][nt][3] + bb.y);
            }
        }
    } else {
        __syncthreads();
        __nv_bfloat16* stage = (__nv_bfloat16*)gsm;
#pragma unroll
        for (int mt = 0; mt < 2; mt++) {
#pragma unroll
            for (int nt = 0; nt < 8; nt++) {
                int rl = wm * 32 + mt * 16 + r0;
                int cl = wn * 64 + nt * 8 + c0;
                float2 bb = *(const float2*)(bias + n0 + cl);
                stage[cl       * 136 + rl]     = __float2bfloat16(acc[mt][nt][0] + bb.x);
                stage[(cl + 1) * 136 + rl]     = __float2bfloat16(acc[mt][nt][1] + bb.y);
                stage[cl       * 136 + rl + 8] = __float2bfloat16(acc[mt][nt][2] + bb.x);
                stage[(cl + 1) * 136 + rl + 8] = __float2bfloat16(acc[mt][nt][3] + bb.y);
            }
        }
        __syncthreads();
        const int bI = m0 >> 11, lI = m0 & (LL - 1);
        const int drow = tid >> 1, seg = tid & 1;
        const int hI = (n0 + drow) >> 6, dI = (n0 + drow) & 63;
        const uint4* src = (const uint4*)(stage + drow * 136 + seg * 64);
        uint4* dst = (uint4*)(vt + (((size_t)bI * HH + hI) * DHD + dI) * LL
                              + lI + seg * 64);
#pragma unroll
        for (int i = 0; i < 8; i++) dst[i] = src[i];
    }
}

// Output projection GEMM (fp32 out). grid (8, 64).
__global__ __launch_bounds__(256) void gemm_o(
    const __nv_bfloat16* __restrict__ A2, const __nv_bfloat16* __restrict__ W2,
    const float* __restrict__ bias, float* __restrict__ C)
{
    extern __shared__ __align__(16) char gsm[];

    const int tid  = threadIdx.x;
    const int lane = tid & 31;
    const int w    = tid >> 5;
    const int wm   = w & 3;
    const int wn   = w >> 2;
    const int m0   = blockIdx.y * 128;
    const int n0   = blockIdx.x * 128;

    float acc[2][8][4];
#pragma unroll
    for (int i = 0; i < 2; i++)
#pragma unroll
        for (int j = 0; j < 8; j++)
#pragma unroll
            for (int l = 0; l < 4; l++) acc[i][j][l] = 0.0f;

    gemm_mainloop(A2, W2, m0, n0, smem_u32(gsm), tid, lane, wm, wn, acc);

    const int r0 = lane >> 2;
    const int c0 = (lane & 3) * 2;
#pragma unroll
    for (int mt = 0; mt < 2; mt++) {
#pragma unroll
        for (int nt = 0; nt < 8; nt++) {
            int row = m0 + wm * 32 + mt * 16 + r0;
            int col = n0 + wn * 64 + nt * 8 + c0;
            float2 bb = *(const float2*)(bias + col);
            float2 v0 = { acc[mt][nt][0] + bb.x, acc[mt][nt][1] + bb.y };
            float2 v1 = { acc[mt][nt][2] + bb.x, acc[mt][nt][3] + bb.y };
            *(float2*)(C + (size_t)row * DD + col)       = v0;
            *(float2*)(C + (size_t)(row + 8) * DD + col) = v1;
        }
    }
}

// ---------------------------------------------------------------------------
// Flash attention v3 (R14): fused QK->exp->PV; 2 CTAs/SM; plain bf16 out.
// ---------------------------------------------------------------------------
#define QP 144
#define VP 272
#define SQ_OFF 0
#define SQ_SZ  (128*QP)
#define SK_OFF SQ_SZ
#define SK_SZ  (128*QP)
#define SV_OFF (SK_OFF + 2*SK_SZ)
#define SV_SZ  (64*VP)
#define MS_OFF (SV_OFF + 2*SV_SZ)
#define FL_SMEM (MS_OFF + 2*512)   // 91136

__global__ __launch_bounds__(256, 2) void flash_tc(
    const __nv_bfloat16* __restrict__ Qb, const __nv_bfloat16* __restrict__ Kb,
    const __nv_bfloat16* __restrict__ Vt, const float* __restrict__ mad,
    __nv_bfloat16* __restrict__ att)
{
    extern __shared__ __align__(16) char dyn[];

    const int b = blockIdx.z, h = blockIdx.y;
    const int q0 = blockIdx.x * 128;
    const int tid = threadIdx.x, lane = tid & 31, w = tid >> 5;
    const size_t bh = (size_t)b * HH + h;
    const uint32_t dynb = smem_u32(dyn);

    const char* ksrc0 = (const char*)(Kb + bh * LL * 64);
    const char* vsrc0 = (const char*)(Vt + bh * DHD * LL);
    const char* msrc0 = (const char*)(mad + b * LL);

    auto issue_tile = [&](int t, int buf) {
        const uint32_t kb = dynb + SK_OFF + buf * SK_SZ;
        const uint32_t vb = dynb + SV_OFF + buf * SV_SZ;
        const char* ks = ksrc0 + (size_t)t * 128 * 128;
#pragma unroll
        for (int j = 0; j < 4; j++) {
            int i = tid + 256 * j;
            int r = i >> 3, s = i & 7;
            CP16(kb + r * QP + s * 16, ks + r * 128 + s * 16);
        }
#pragma unroll
        for (int j = 0; j < 4; j++) {
            int i = tid + 256 * j;
            int r = i >> 4, s = i & 15;
            CP16(vb + r * VP + s * 16,
                 vsrc0 + ((size_t)r * LL + t * 128) * 2 + s * 16);
        }
        if (tid < 32)
            CP16(dynb + MS_OFF + buf * 512 + tid * 16,
                 msrc0 + (size_t)t * 512 + tid * 16);
    };

    {
        const char* qsrc = (const char*)(Qb + (bh * LL + q0) * 64);
#pragma unroll
        for (int j = 0; j < 4; j++) {
            int i = tid + 256 * j;
            int r = i >> 3, s = i & 7;
            *(uint4*)(dyn + SQ_OFF + r * QP + s * 16) =
                *(const uint4*)(qsrc + r * 128 + s * 16);
        }
    }
    issue_tile(0, 0);
    CP_COMMIT();
    __syncthreads();

    uint32_t qf[4][4];
    {
        uint32_t base = dynb + SQ_OFF + (w * 16 + (lane & 15)) * QP + (lane >> 4) * 16;
#pragma unroll
        for (int ks = 0; ks < 4; ks++) ldm_x4(base + ks * 32, qf[ks]);
    }

    float O[8][4];
#pragma unroll
    for (int g = 0; g < 8; g++)
#pragma unroll
        for (int l = 0; l < 4; l++) O[g][l] = 0.0f;
    float La[4] = {0.f, 0.f, 0.f, 0.f};

    const int c0 = (lane & 3) * 2;

    #pragma unroll 1
    for (int t = 0; t < LL / 128; t++) {
        const int buf = t & 1;
        if (t + 1 < LL / 128) {
            issue_tile(t + 1, buf ^ 1);
            CP_COMMIT();
            CP_WAIT1();
        } else {
            CP_WAIT0();
        }
        __syncthreads();

        const float* Msf = (const float*)(dyn + MS_OFF + buf * 512);
        const uint32_t kbase = dynb + SK_OFF + buf * SK_SZ
                             + (lane & 15) * QP + (lane >> 4) * 16;
        const uint32_t vbase = dynb + SV_OFF + buf * SV_SZ
                             + (lane & 15) * VP + (lane >> 4) * 16;

#pragma unroll
        for (int j = 0; j < 8; j++) {
            float a0[4] = {0, 0, 0, 0}, a1[4] = {0, 0, 0, 0};
#pragma unroll
            for (int ks = 0; ks < 4; ks++) {
                uint32_t bf[4];
                ldm_x4(kbase + j * 16 * QP + ks * 32, bf);
                mma16816(a0, qf[ks], bf[0], bf[2]);
                mma16816(a1, qf[ks], bf[1], bf[3]);
            }

            int key = j * 16 + c0;
            float ad0 = Msf[key],     ad1 = Msf[key + 1];
            float ad2 = Msf[key + 8], ad3 = Msf[key + 9];
            a0[0] = ex2f(fmaf(a0[0], SM_C2, ad0));
            a0[1] = ex2f(fmaf(a0[1], SM_C2, ad1));
            a0[2] = ex2f(fmaf(a0[2], SM_C2, ad0));
            a0[3] = ex2f(fmaf(a0[3], SM_C2, ad1));
            a1[0] = ex2f(fmaf(a1[0], SM_C2, ad2));
            a1[1] = ex2f(fmaf(a1[1], SM_C2, ad3));
            a1[2] = ex2f(fmaf(a1[2], SM_C2, ad2));
            a1[3] = ex2f(fmaf(a1[3], SM_C2, ad3));

            uint32_t a[4];
            a[0] = pack_bf162(a0[0], a0[1]);
            a[1] = pack_bf162(a0[2], a0[3]);
            a[2] = pack_bf162(a1[0], a1[1]);
            a[3] = pack_bf162(a1[2], a1[3]);
            mma16816(La, a, ONESF, ONESF);
#pragma unroll
            for (int g = 0; g < 4; g++) {
                uint32_t bf[4];
                ldm_x4(vbase + g * 16 * VP + j * 32, bf);
                mma16816(O[2*g],     a, bf[0], bf[2]);
                mma16816(O[2*g + 1], a, bf[1], bf[3]);
            }
        }
        __syncthreads();
    }

    // normalize + write plain bf16 att [8192, 1024]
    float inv0 = 1.0f / La[0], inv1 = 1.0f / La[2];
    const int r0 = lane >> 2;
    const size_t row0 = (size_t)b * LL + q0 + w * 16 + r0;
    __nv_bfloat162* C = (__nv_bfloat162*)att;
#pragma unroll
    for (int g = 0; g < 8; g++) {
        int d = 8 * g + c0;
        size_t idx = (row0 * DD + h * DHD + d) >> 1;
        C[idx] = __floats2bfloat162_rn(O[g][0] * inv0, O[g][1] * inv0);
        C[idx + 8 * (DD / 2)] = __floats2bfloat162_rn(O[g][2] * inv1,
                                                      O[g][3] * inv1);
    }
}

// ---------------------------------------------------------------------------
// Residual + LayerNorm
// ---------------------------------------------------------------------------
__global__ __launch_bounds__(256) void ln_kernel(
    const float* __restrict__ proj, const float* __restrict__ resid,
    const float* __restrict__ gamma, const float* __restrict__ beta,
    float* __restrict__ out)
{
    const int row = blockIdx.x;
    const int tid = threadIdx.x;

    float4 p = ((const float4*)(proj  + row * DD))[tid];
    float4 r = ((const float4*)(resid + row * DD))[tid];
    float4 x = make_float4(p.x + r.x, p.y + r.y, p.z + r.z, p.w + r.w);

    float s  = x.x + x.y + x.z + x.w;
    float ss = x.x * x.x + x.y * x.y + x.z * x.z + x.w * x.w;

#pragma unroll
    for (int off = 16; off > 0; off >>= 1) {
        s  += __shfl_xor_sync(0xffffffffu, s,  off);
        ss += __shfl_xor_sync(0xffffffffu, ss, off);
    }

    __shared__ float rs[8], rss[8];
    __shared__ float mu_s, rstd_s;
    const int wid  = tid >> 5;
    const int lane = tid & 31;
    if (lane == 0) { rs[wid] = s; rss[wid] = ss; }
    __syncthreads();
    if (tid == 0) {
        float S = 0.f, SS = 0.f;
#pragma unroll
        for (int i = 0; i < 8; i++) { S += rs[i]; SS += rss[i]; }
        float mu  = S * (1.0f / DD);
        float var = SS * (1.0f / DD) - mu * mu;
        mu_s   = mu;
        rstd_s = rsqrtf(var + 1e-5f);
    }
    __syncthreads();

    float mu = mu_s, rstd = rstd_s;
    float4 g  = ((const float4*)gamma)[tid];
    float4 be = ((const float4*)beta)[tid];
    float4 o;
    o.x = (x.x - mu) * rstd * g.x + be.x;
    o.y = (x.y - mu) * rstd * g.y + be.y;
    o.z = (x.z - mu) * rstd * g.z + be.z;
    o.w = (x.w - mu) * rstd * g.w + be.w;
    ((float4*)(out + row * DD))[tid] = o;
}

// ---------------------------------------------------------------------------
extern "C" void kernel_launch(void* const* d_in, const int* in_sizes, int n_in,
                              void* d_out, int out_size)
{
    const float* query = (const float*)d_in[0];
    const float* key_  = (const float*)d_in[1];
    const float* value = (const float*)d_in[2];
    const int*   mask  = (const int*  )d_in[3];
    const float* Wq    = (const float*)d_in[4];
    const float* bq    = (const float*)d_in[5];
    const float* Wk    = (const float*)d_in[6];
    const float* bk    = (const float*)d_in[7];
    const float* Wv    = (const float*)d_in[8];
    const float* bv    = (const float*)d_in[9];
    const float* Wo    = (const float*)d_in[10];
    const float* bo    = (const float*)d_in[11];
    const float* gamma = (const float*)d_in[12];
    const float* beta  = (const float*)d_in[13];
    float* out = (float*)d_out;

    float *proj, *mad;
    cudaGetSymbolAddress((void**)&proj, g_proj);
    cudaGetSymbolAddress((void**)&mad,  g_mad);
    __nv_bfloat16 *qc, *kc, *vc, *att, *Wqc, *Wkc, *Wvc, *Woc, *qbf, *kbf, *vt;
    cudaGetSymbolAddress((void**)&qc,   g_qc);
    cudaGetSymbolAddress((void**)&kc,   g_kc);
    cudaGetSymbolAddress((void**)&vc,   g_vc);
    cudaGetSymbolAddress((void**)&att,  g_att);
    cudaGetSymbolAddress((void**)&Wqc,  g_Wqc);
    cudaGetSymbolAddress((void**)&Wkc,  g_Wkc);
    cudaGetSymbolAddress((void**)&Wvc,  g_Wvc);
    cudaGetSymbolAddress((void**)&Woc,  g_Woc);
    cudaGetSymbolAddress((void**)&qbf,  g_qbf);
    cudaGetSymbolAddress((void**)&kbf,  g_kbf);
    cudaGetSymbolAddress((void**)&vt,   g_vt);

    cudaFuncSetAttribute(flash_tc,
        cudaFuncAttributeMaxDynamicSharedMemorySize, FL_SMEM);
    cudaFuncSetAttribute(gemm_qkv,
        cudaFuncAttributeMaxDynamicSharedMemorySize, GM_SMEM);
    cudaFuncSetAttribute(gemm_o,
        cudaFuncAttributeMaxDynamicSharedMemorySize, GM_SMEM);

    const int nInp4 = ROWS * DD / 4;
    const int nW4   = DD * DD / 4;
    cast3_kernel<<<dim3((nInp4 + 255) / 256, 3), 256>>>(
        query, key_, value, qc, kc, vc, nInp4);
    cast4_kernel<<<dim3((nW4 + 255) / 256, 4), 256>>>(
        Wq, Wk, Wv, Wo, Wqc, Wkc, Wvc, Woc, nW4);
    mask_kernel<<<(BB * LL + 255) / 256, 256>>>(mask, mad);

    dim3 qkvgrid(DD / 128, ROWS / 128, 3);   // (8, 64, 3)
    gemm_qkv<<<qkvgrid, 256, GM_SMEM>>>(
        qc, kc, vc, Wqc, Wkc, Wvc, bq, bk, bv, qbf, kbf, vt);

    dim3 fgrid(LL / 128, HH, BB);            // (16, 16, 4)
    flash_tc<<<fgrid, 256, FL_SMEM>>>(qbf, kbf, vt, mad, att);

    dim3 ogrid(DD / 128, ROWS / 128);        // (8, 64)
    gemm_o<<<ogrid, 256, GM_SMEM>>>(att, Woc, bo, proj);

    ln_kernel<<<ROWS, 256>>>(proj, query, gamma, beta, out);
}